// round 9
// baseline (speedup 1.0000x reference)
#include <cuda_runtime.h>
#include <math.h>

#define MAXN 100000
#define MAXE 3200000
#define NG 256

// ---------------- device scratch (no allocations allowed) ----------------
__device__ int    g_is32_ei;            // 1 if edge_index is int32, 0 if int64
__device__ int    g_is32_b;             // 1 if batch is int32, 0 if int64
__device__ int    g_deg[MAXN];          // edge-only in-degree
__device__ int    g_rowp[MAXN];         // CSR row start (exclusive prefix of deg)
__device__ int    g_cursor[MAXN];       // placement cursors
__device__ int    g_bsum[512];          // block sums for 2-level scan
__device__ int    g_perm[MAXE];         // src node id, grouped by dst
__device__ float  g_dinv[MAXN];         // rsqrt(deg+1)
__device__ float4 g_g1[MAXN * 4];       // layer1 pre-scaled features g1 = h1*dinv  [N,16]
__device__ float4 g_g2[MAXN * 4];       // layer2 pre-scaled features g2 = h2*dinv  [N,16]
__device__ float4 g_pool[NG * 4];       // per-graph sums [256,16]
__device__ int    g_cnt[NG];            // per-graph node counts

__device__ __forceinline__ void red_add_v4(float4* addr, float4 v) {
    asm volatile("red.global.add.v4.f32 [%0], {%1,%2,%3,%4};"
                 :: "l"(addr), "f"(v.x), "f"(v.y), "f"(v.z), "f"(v.w)
                 : "memory");
}
__device__ __forceinline__ float4 f4_fma(float s, float4 w, float4 a) {
    a.x = fmaf(s, w.x, a.x); a.y = fmaf(s, w.y, a.y);
    a.z = fmaf(s, w.z, a.z); a.w = fmaf(s, w.w, a.w);
    return a;
}
__device__ __forceinline__ float4 f4_scale(float4 a, float s) {
    return make_float4(a.x * s, a.y * s, a.z * s, a.w * s);
}
__device__ __forceinline__ float4 f4_add(float4 a, float4 b) {
    return make_float4(a.x + b.x, a.y + b.y, a.z + b.z, a.w + b.w);
}
__device__ __forceinline__ int clampi(int v, int hi) { return min(max(v, 0), hi - 1); }
// dtype-aware index load (int32 or int64 buffer), clamped to [0, hi)
__device__ __forceinline__ int load_idx(const void* p, long long i, int is32, int hi) {
    int v = is32 ? ((const int*)p)[i] : (int)((const long long*)p)[i];
    return clampi(v, hi);
}

// ---------------- kernels ----------------

__global__ void __launch_bounds__(256) k_init(int N) {
    int i = blockIdx.x * blockDim.x + threadIdx.x;
    if (i < N)      g_deg[i] = 0;
    if (i < NG * 4) g_pool[i] = make_float4(0.f, 0.f, 0.f, 0.f);
    if (i < NG)     g_cnt[i]  = 0;
    if (i == 0) { g_is32_ei = 0; g_is32_b = 0; }
}

// dtype probe: odd dwords of int64 index data (< 2^31) are all zero.
template <int WHICH>
__global__ void __launch_bounds__(256) k_detect(const unsigned* __restrict__ buf,
                                                long long off, int nsamp, long long stride) {
    int k = blockIdx.x * blockDim.x + threadIdx.x;
    int v = 0;
    if (k < nsamp) v = (buf[off + 2LL * k * stride + 1] != 0u) ? 1 : 0;
    int any = __syncthreads_or(v);
    if (threadIdx.x == 0 && any) {
        if (WHICH == 0) atomicOr(&g_is32_ei, 1);
        else            atomicOr(&g_is32_b, 1);
    }
}

// degree count: 4 edges per thread for MLP (int4 fast path when E%4==0)
__global__ void __launch_bounds__(256) k_deg(const void* __restrict__ ei, int E, int N) {
    int t = blockIdx.x * blockDim.x + threadIdx.x;
    int e0 = t * 4;
    if (e0 >= E) return;
    if (g_is32_ei) {
        const int* dst = (const int*)ei + E;
        if ((E & 3) == 0) {
            int4 d4 = __ldg((const int4*)dst + t);
            atomicAdd(&g_deg[clampi(d4.x, N)], 1);
            atomicAdd(&g_deg[clampi(d4.y, N)], 1);
            atomicAdd(&g_deg[clampi(d4.z, N)], 1);
            atomicAdd(&g_deg[clampi(d4.w, N)], 1);
        } else {
            #pragma unroll
            for (int k = 0; k < 4; k++)
                if (e0 + k < E) atomicAdd(&g_deg[clampi(__ldg(dst + e0 + k), N)], 1);
        }
    } else {
        const long long* dst = (const long long*)ei + E;
        #pragma unroll
        for (int k = 0; k < 4; k++)
            if (e0 + k < E) atomicAdd(&g_deg[clampi((int)__ldg(dst + e0 + k), N)], 1);
    }
}

// 2-level exclusive scan of g_deg -> g_rowp
__global__ void __launch_bounds__(256) k_scan1(int N) {
    __shared__ int sh[256];
    int t = threadIdx.x;
    int i = blockIdx.x * 256 + t;
    int v = (i < N) ? g_deg[i] : 0;
    sh[t] = v;
    __syncthreads();
    for (int off = 1; off < 256; off <<= 1) {
        int add = (t >= off) ? sh[t - off] : 0;
        __syncthreads();
        sh[t] += add;
        __syncthreads();
    }
    if (i < N) g_rowp[i] = sh[t] - v;            // exclusive within block
    if (t == 255) g_bsum[blockIdx.x] = sh[255];  // block total
}

__global__ void __launch_bounds__(512) k_scan2(int nb) {
    __shared__ int sh[512];
    int t = threadIdx.x;
    int v = (t < nb) ? g_bsum[t] : 0;
    sh[t] = v;
    __syncthreads();
    for (int off = 1; off < 512; off <<= 1) {
        int add = (t >= off) ? sh[t - off] : 0;
        __syncthreads();
        sh[t] += add;
        __syncthreads();
    }
    if (t < nb) g_bsum[t] = sh[t] - v;           // exclusive block offsets
}

__global__ void __launch_bounds__(256) k_scan3(int N) {
    int i = blockIdx.x * blockDim.x + threadIdx.x;
    if (i >= N) return;
    int r = g_rowp[i] + g_bsum[i >> 8];
    g_rowp[i]   = r;
    g_cursor[i] = r;
    g_dinv[i]   = rsqrtf((float)(g_deg[i] + 1));  // +1 self loop
}

// place src ids grouped by dst: 4 edges/thread for MLP
__global__ void __launch_bounds__(256) k_place(const void* __restrict__ ei, int E, int N) {
    int t = blockIdx.x * blockDim.x + threadIdx.x;
    int e0 = t * 4;
    if (e0 >= E) return;
    if (g_is32_ei) {
        const int* src = (const int*)ei;
        const int* dst = src + E;
        if ((E & 3) == 0) {
            int4 s4 = __ldg((const int4*)src + t);
            int4 d4 = __ldg((const int4*)dst + t);
            g_perm[atomicAdd(&g_cursor[clampi(d4.x, N)], 1)] = clampi(s4.x, N);
            g_perm[atomicAdd(&g_cursor[clampi(d4.y, N)], 1)] = clampi(s4.y, N);
            g_perm[atomicAdd(&g_cursor[clampi(d4.z, N)], 1)] = clampi(s4.z, N);
            g_perm[atomicAdd(&g_cursor[clampi(d4.w, N)], 1)] = clampi(s4.w, N);
        } else {
            #pragma unroll
            for (int k = 0; k < 4; k++)
                if (e0 + k < E) {
                    int s = clampi(__ldg(src + e0 + k), N);
                    int d = clampi(__ldg(dst + e0 + k), N);
                    g_perm[atomicAdd(&g_cursor[d], 1)] = s;
                }
        }
    } else {
        const long long* src = (const long long*)ei;
        const long long* dst = src + E;
        #pragma unroll
        for (int k = 0; k < 4; k++)
            if (e0 + k < E) {
                int s = clampi((int)__ldg(src + e0 + k), N);
                int d = clampi((int)__ldg(dst + e0 + k), N);
                g_perm[atomicAdd(&g_cursor[d], 1)] = s;
            }
    }
}

// g1 = (x @ W1) * dinv
__global__ void __launch_bounds__(256) k_gemm1(const float* __restrict__ x,
                                               const float* __restrict__ W1, int N) {
    __shared__ float4 Ws[512];   // W1 as [128 rows][4 float4-cols]
    int t = threadIdx.x;
    Ws[t]       = ((const float4*)W1)[t];
    Ws[t + 256] = ((const float4*)W1)[t + 256];
    __syncthreads();

    int n = blockIdx.x * 256 + t;
    if (n >= N) return;

    float4 a0 = make_float4(0.f, 0.f, 0.f, 0.f);
    float4 a1 = a0, a2 = a0, a3 = a0;
    const float4* xr = (const float4*)(x + (size_t)n * 128);

#pragma unroll 4
    for (int k4 = 0; k4 < 32; k4++) {
        float4 xv = __ldg(&xr[k4]);
        const float4* w = &Ws[(k4 * 4) * 4];
        a0 = f4_fma(xv.x, w[0],  a0); a1 = f4_fma(xv.x, w[1],  a1);
        a2 = f4_fma(xv.x, w[2],  a2); a3 = f4_fma(xv.x, w[3],  a3);
        a0 = f4_fma(xv.y, w[4],  a0); a1 = f4_fma(xv.y, w[5],  a1);
        a2 = f4_fma(xv.y, w[6],  a2); a3 = f4_fma(xv.y, w[7],  a3);
        a0 = f4_fma(xv.z, w[8],  a0); a1 = f4_fma(xv.z, w[9],  a1);
        a2 = f4_fma(xv.z, w[10], a2); a3 = f4_fma(xv.z, w[11], a3);
        a0 = f4_fma(xv.w, w[12], a0); a1 = f4_fma(xv.w, w[13], a1);
        a2 = f4_fma(xv.w, w[14], a2); a3 = f4_fma(xv.w, w[15], a3);
    }

    float di = g_dinv[n];
    g_g1[n * 4 + 0] = f4_scale(a0, di); g_g1[n * 4 + 1] = f4_scale(a1, di);
    g_g1[n * 4 + 2] = f4_scale(a2, di); g_g1[n * 4 + 3] = f4_scale(a3, di);
}

// segmented sum of g over node's incoming edges, seeded with self-loop g[n].
// Unrolled by 4 for gather MLP (avg degree ~32).
__device__ __forceinline__ float4 seg_sum(const float4* __restrict__ g, int n, int q) {
    int start = g_rowp[n];
    int end   = start + g_deg[n];
    float4 acc = g[(size_t)n * 4 + q];          // self loop
    int e = start;
    for (; e + 4 <= end; e += 4) {
        int s0 = __ldg(&g_perm[e]);
        int s1 = __ldg(&g_perm[e + 1]);
        int s2 = __ldg(&g_perm[e + 2]);
        int s3 = __ldg(&g_perm[e + 3]);
        float4 v0 = __ldg(&g[(size_t)s0 * 4 + q]);
        float4 v1 = __ldg(&g[(size_t)s1 * 4 + q]);
        float4 v2 = __ldg(&g[(size_t)s2 * 4 + q]);
        float4 v3 = __ldg(&g[(size_t)s3 * 4 + q]);
        acc = f4_add(acc, f4_add(f4_add(v0, v1), f4_add(v2, v3)));
    }
    for (; e < end; e++) {
        int s0 = __ldg(&g_perm[e]);
        acc = f4_add(acc, __ldg(&g[(size_t)s0 * 4 + q]));
    }
    return acc;
}

// reduce layer1 + fused: t = relu(dinv*acc + b1); h2 = t @ W2; g2 = h2*dinv
// NOTE: no early return (shuffles need full warps); stores predicated.
__global__ void __launch_bounds__(256) k_reduce1(const float* __restrict__ b1,
                                                 const float* __restrict__ W2, int N) {
    __shared__ float4 W2s[64];
    __shared__ float4 b1s[4];
    int t = threadIdx.x;
    if (t < 64) W2s[t] = ((const float4*)W2)[t];
    if (t < 4)  b1s[t] = ((const float4*)b1)[t];
    __syncthreads();

    int gid = blockIdx.x * 256 + t;
    int n = gid >> 2;
    int q = gid & 3;
    bool valid = (n < N);
    int nc = valid ? n : (N - 1);

    float4 acc = seg_sum(g_g1, nc, q);
    float di = g_dinv[nc];
    float4 o = f4_fma(di, acc, b1s[q]);          // dinv*acc + b1
    float tv0 = fmaxf(o.x, 0.f), tv1 = fmaxf(o.y, 0.f);
    float tv2 = fmaxf(o.z, 0.f), tv3 = fmaxf(o.w, 0.f);

    // 16x16 GEMM across the quad via shuffles
    float4 a = make_float4(0.f, 0.f, 0.f, 0.f);
    int lane = threadIdx.x & 31;
    int base = lane & ~3;
#pragma unroll
    for (int j = 0; j < 16; j++) {
        float src = (j & 3) == 0 ? tv0 : (j & 3) == 1 ? tv1 : (j & 3) == 2 ? tv2 : tv3;
        float tj = __shfl_sync(0xFFFFFFFFu, src, base + (j >> 2));
        a = f4_fma(tj, W2s[j * 4 + q], a);
    }
    if (valid) g_g2[(size_t)n * 4 + q] = f4_scale(a, di);
}

// reduce layer2 + fused mean-pool accumulate
__global__ void __launch_bounds__(256) k_reduce2(const void* __restrict__ batch,
                                                 const float* __restrict__ b2, int N) {
    int gid = blockIdx.x * blockDim.x + threadIdx.x;
    int n = gid >> 2;
    int q = gid & 3;
    if (n >= N) return;

    float4 acc = seg_sum(g_g2, n, q);
    float di = g_dinv[n];
    float4 y = f4_fma(di, acc, __ldg(&((const float4*)b2)[q]));  // dinv*acc + b2

    int b = load_idx(batch, n, g_is32_b, NG);
    red_add_v4(&g_pool[b * 4 + q], y);
    if (q == 0) atomicAdd(&g_cnt[b], 1);
}

__global__ void __launch_bounds__(256) k_final(float* __restrict__ out) {
    int i = blockIdx.x * blockDim.x + threadIdx.x;
    if (i >= NG * 16) return;
    int g = i >> 4;
    float c = fmaxf((float)g_cnt[g], 1.0f);
    float s = ((const float*)g_pool)[i] / c;
    out[i] = 1.0f / (1.0f + expf(-s));
}

// ---------------- launch ----------------
extern "C" void kernel_launch(void* const* d_in, const int* in_sizes, int n_in,
                              void* d_out, int out_size) {
    const float* x     = (const float*)d_in[0];
    const void*  ei    = d_in[1];               // [2, E] int32 OR int64 (probed)
    const void*  batch = d_in[2];               // [N]    int32 OR int64 (probed)
    const float* W1    = (const float*)d_in[3];
    const float* b1    = (const float*)d_in[4];
    const float* W2    = (const float*)d_in[5];
    const float* b2    = (const float*)d_in[6];
    float* out = (float*)d_out;

    int N = in_sizes[0] / 128;
    int E = in_sizes[1] / 2;

    int nb_nodes = (N + 255) / 256;
    int nb_edge4 = (E / 4 + 256) / 256;          // 4 edges per thread (covers tail)
    int nb_node4 = (4 * N + 255) / 256;

    k_init<<<nb_nodes, 256>>>(N);

    // dtype probes
    {
        int nsamp = E / 64;
        if (nsamp > 0)
            k_detect<0><<<(nsamp + 255) / 256, 256>>>((const unsigned*)ei, 0, nsamp, 64);
    }
    {
        long long off = (N > 4096) ? (long long)((N - 4096) & ~1) : 0;
        int nsamp = (int)((N - off) / 2);
        if (nsamp > 0)
            k_detect<1><<<(nsamp + 255) / 256, 256>>>((const unsigned*)batch, off, nsamp, 1);
    }

    // CSR build
    k_deg<<<nb_edge4, 256>>>(ei, E, N);
    k_scan1<<<nb_nodes, 256>>>(N);
    k_scan2<<<1, 512>>>(nb_nodes);
    k_scan3<<<nb_nodes, 256>>>(N);
    k_place<<<nb_edge4, 256>>>(ei, E, N);

    // pipeline
    k_gemm1<<<nb_nodes, 256>>>(x, W1, N);
    k_reduce1<<<nb_node4, 256>>>(b1, W2, N);
    k_reduce2<<<nb_node4, 256>>>(batch, b2, N);
    k_final<<<(NG * 16 + 255) / 256, 256>>>(out);
}

// round 10
// speedup vs baseline: 1.0843x; 1.0843x over previous
#include <cuda_runtime.h>
#include <math.h>

#define MAXN 100000
#define MAXE 3200000
#define NG 256

// ---------------- device scratch (no allocations allowed) ----------------
__device__ int    g_is32_ei;            // 1 if edge_index is int32, 0 if int64
__device__ int    g_is32_b;             // 1 if batch is int32, 0 if int64
__device__ int    g_deg[MAXN];          // edge-only in-degree
__device__ int    g_rowp[MAXN];         // CSR row start (exclusive prefix of deg)
__device__ int    g_cursor[MAXN];       // placement cursors
__device__ int    g_bsum[512];          // block sums for 2-level scan
__device__ int    g_perm[MAXE];         // src node id, grouped by dst
__device__ float  g_dinv[MAXN];         // rsqrt(deg+1)
__device__ float4 g_g1[MAXN * 4];       // layer1 pre-scaled features g1 = h1*dinv  [N,16]
__device__ float4 g_g2[MAXN * 4];       // layer2 pre-scaled features g2 = h2*dinv  [N,16]
__device__ float4 g_pool[NG * 4];       // per-graph sums [256,16]
__device__ int    g_cnt[NG];            // per-graph node counts

__device__ __forceinline__ void red_add_v4(float4* addr, float4 v) {
    asm volatile("red.global.add.v4.f32 [%0], {%1,%2,%3,%4};"
                 :: "l"(addr), "f"(v.x), "f"(v.y), "f"(v.z), "f"(v.w)
                 : "memory");
}
__device__ __forceinline__ float4 f4_fma(float s, float4 w, float4 a) {
    a.x = fmaf(s, w.x, a.x); a.y = fmaf(s, w.y, a.y);
    a.z = fmaf(s, w.z, a.z); a.w = fmaf(s, w.w, a.w);
    return a;
}
__device__ __forceinline__ float4 f4_scale(float4 a, float s) {
    return make_float4(a.x * s, a.y * s, a.z * s, a.w * s);
}
__device__ __forceinline__ float4 f4_add(float4 a, float4 b) {
    return make_float4(a.x + b.x, a.y + b.y, a.z + b.z, a.w + b.w);
}
__device__ __forceinline__ int clampi(int v, int hi) { return min(max(v, 0), hi - 1); }
__device__ __forceinline__ int load_idx(const void* p, long long i, int is32, int hi) {
    int v = is32 ? ((const int*)p)[i] : (int)((const long long*)p)[i];
    return clampi(v, hi);
}

// ---------------- kernels ----------------

__global__ void __launch_bounds__(256) k_init(int N) {
    int i = blockIdx.x * blockDim.x + threadIdx.x;
    if (i < N)      g_deg[i] = 0;
    if (i < NG * 4) g_pool[i] = make_float4(0.f, 0.f, 0.f, 0.f);
    if (i < NG)     g_cnt[i]  = 0;
    if (i == 0) { g_is32_ei = 0; g_is32_b = 0; }
}

// dtype probe: odd dwords of int64 index data (< 2^31) are all zero.
template <int WHICH>
__global__ void __launch_bounds__(256) k_detect(const unsigned* __restrict__ buf,
                                                long long off, int nsamp, long long stride) {
    int k = blockIdx.x * blockDim.x + threadIdx.x;
    int v = 0;
    if (k < nsamp) v = (buf[off + 2LL * k * stride + 1] != 0u) ? 1 : 0;
    int any = __syncthreads_or(v);
    if (threadIdx.x == 0 && any) {
        if (WHICH == 0) atomicOr(&g_is32_ei, 1);
        else            atomicOr(&g_is32_b, 1);
    }
}

// degree count: 4 edges per thread (int4 fast path when E%4==0)
__global__ void __launch_bounds__(256) k_deg(const void* __restrict__ ei, int E, int N) {
    int t = blockIdx.x * blockDim.x + threadIdx.x;
    int e0 = t * 4;
    if (e0 >= E) return;
    if (g_is32_ei) {
        const int* dst = (const int*)ei + E;
        if ((E & 3) == 0) {
            int4 d4 = __ldg((const int4*)dst + t);
            atomicAdd(&g_deg[clampi(d4.x, N)], 1);
            atomicAdd(&g_deg[clampi(d4.y, N)], 1);
            atomicAdd(&g_deg[clampi(d4.z, N)], 1);
            atomicAdd(&g_deg[clampi(d4.w, N)], 1);
        } else {
            #pragma unroll
            for (int k = 0; k < 4; k++)
                if (e0 + k < E) atomicAdd(&g_deg[clampi(__ldg(dst + e0 + k), N)], 1);
        }
    } else {
        const long long* dst = (const long long*)ei + E;
        #pragma unroll
        for (int k = 0; k < 4; k++)
            if (e0 + k < E) atomicAdd(&g_deg[clampi((int)__ldg(dst + e0 + k), N)], 1);
    }
}

// 2-level exclusive scan of g_deg -> g_rowp
__global__ void __launch_bounds__(256) k_scan1(int N) {
    __shared__ int sh[256];
    int t = threadIdx.x;
    int i = blockIdx.x * 256 + t;
    int v = (i < N) ? g_deg[i] : 0;
    sh[t] = v;
    __syncthreads();
    for (int off = 1; off < 256; off <<= 1) {
        int add = (t >= off) ? sh[t - off] : 0;
        __syncthreads();
        sh[t] += add;
        __syncthreads();
    }
    if (i < N) g_rowp[i] = sh[t] - v;
    if (t == 255) g_bsum[blockIdx.x] = sh[255];
}

__global__ void __launch_bounds__(512) k_scan2(int nb) {
    __shared__ int sh[512];
    int t = threadIdx.x;
    int v = (t < nb) ? g_bsum[t] : 0;
    sh[t] = v;
    __syncthreads();
    for (int off = 1; off < 512; off <<= 1) {
        int add = (t >= off) ? sh[t - off] : 0;
        __syncthreads();
        sh[t] += add;
        __syncthreads();
    }
    if (t < nb) g_bsum[t] = sh[t] - v;
}

__global__ void __launch_bounds__(256) k_scan3(int N) {
    int i = blockIdx.x * blockDim.x + threadIdx.x;
    if (i >= N) return;
    int r = g_rowp[i] + g_bsum[i >> 8];
    g_rowp[i]   = r;
    g_cursor[i] = r;
    g_dinv[i]   = rsqrtf((float)(g_deg[i] + 1));  // +1 self loop
}

// place src ids grouped by dst: 4 edges/thread
__global__ void __launch_bounds__(256) k_place(const void* __restrict__ ei, int E, int N) {
    int t = blockIdx.x * blockDim.x + threadIdx.x;
    int e0 = t * 4;
    if (e0 >= E) return;
    if (g_is32_ei) {
        const int* src = (const int*)ei;
        const int* dst = src + E;
        if ((E & 3) == 0) {
            int4 s4 = __ldg((const int4*)src + t);
            int4 d4 = __ldg((const int4*)dst + t);
            g_perm[atomicAdd(&g_cursor[clampi(d4.x, N)], 1)] = clampi(s4.x, N);
            g_perm[atomicAdd(&g_cursor[clampi(d4.y, N)], 1)] = clampi(s4.y, N);
            g_perm[atomicAdd(&g_cursor[clampi(d4.z, N)], 1)] = clampi(s4.z, N);
            g_perm[atomicAdd(&g_cursor[clampi(d4.w, N)], 1)] = clampi(s4.w, N);
        } else {
            #pragma unroll
            for (int k = 0; k < 4; k++)
                if (e0 + k < E) {
                    int s = clampi(__ldg(src + e0 + k), N);
                    int d = clampi(__ldg(dst + e0 + k), N);
                    g_perm[atomicAdd(&g_cursor[d], 1)] = s;
                }
        }
    } else {
        const long long* src = (const long long*)ei;
        const long long* dst = src + E;
        #pragma unroll
        for (int k = 0; k < 4; k++)
            if (e0 + k < E) {
                int s = clampi((int)__ldg(src + e0 + k), N);
                int d = clampi((int)__ldg(dst + e0 + k), N);
                g_perm[atomicAdd(&g_cursor[d], 1)] = s;
            }
    }
}

// g1 = (x @ W1) * dinv ; 2 nodes per thread to reuse W smem loads
__global__ void __launch_bounds__(256) k_gemm1(const float* __restrict__ x,
                                               const float* __restrict__ W1, int N) {
    __shared__ float4 Ws[512];   // W1 as [128 rows][4 float4-cols]
    int t = threadIdx.x;
    Ws[t]       = ((const float4*)W1)[t];
    Ws[t + 256] = ((const float4*)W1)[t + 256];
    __syncthreads();

    int n0 = blockIdx.x * 512 + t;
    int n1 = n0 + 256;
    bool v0 = (n0 < N), v1 = (n1 < N);
    if (!v0) return;

    float4 a0 = make_float4(0.f, 0.f, 0.f, 0.f);
    float4 a1 = a0, a2 = a0, a3 = a0;
    float4 c0 = a0, c1 = a0, c2 = a0, c3 = a0;
    const float4* xr0 = (const float4*)(x + (size_t)n0 * 128);
    const float4* xr1 = (const float4*)(x + (size_t)(v1 ? n1 : n0) * 128);

#pragma unroll 2
    for (int k4 = 0; k4 < 32; k4++) {
        float4 xa = __ldg(&xr0[k4]);
        float4 xb = __ldg(&xr1[k4]);
        const float4* w = &Ws[(k4 * 4) * 4];
#pragma unroll
        for (int j = 0; j < 4; j++) {
            float sa = (j == 0) ? xa.x : (j == 1) ? xa.y : (j == 2) ? xa.z : xa.w;
            float sb = (j == 0) ? xb.x : (j == 1) ? xb.y : (j == 2) ? xb.z : xb.w;
            float4 w0 = w[j * 4 + 0], w1 = w[j * 4 + 1], w2 = w[j * 4 + 2], w3 = w[j * 4 + 3];
            a0 = f4_fma(sa, w0, a0); a1 = f4_fma(sa, w1, a1);
            a2 = f4_fma(sa, w2, a2); a3 = f4_fma(sa, w3, a3);
            c0 = f4_fma(sb, w0, c0); c1 = f4_fma(sb, w1, c1);
            c2 = f4_fma(sb, w2, c2); c3 = f4_fma(sb, w3, c3);
        }
    }

    float d0 = g_dinv[n0];
    g_g1[n0 * 4 + 0] = f4_scale(a0, d0); g_g1[n0 * 4 + 1] = f4_scale(a1, d0);
    g_g1[n0 * 4 + 2] = f4_scale(a2, d0); g_g1[n0 * 4 + 3] = f4_scale(a3, d0);
    if (v1) {
        float d1 = g_dinv[n1];
        g_g1[n1 * 4 + 0] = f4_scale(c0, d1); g_g1[n1 * 4 + 1] = f4_scale(c1, d1);
        g_g1[n1 * 4 + 2] = f4_scale(c2, d1); g_g1[n1 * 4 + 3] = f4_scale(c3, d1);
    }
}

// segmented sum of g over node's incoming edges, seeded with self-loop g[n]
__device__ __forceinline__ float4 seg_sum(const float4* __restrict__ g, int n, int q) {
    int start = g_rowp[n];
    int end   = start + g_deg[n];
    float4 acc = g[(size_t)n * 4 + q];          // self loop
    int e = start;
    for (; e + 4 <= end; e += 4) {
        int s0 = __ldg(&g_perm[e]);
        int s1 = __ldg(&g_perm[e + 1]);
        int s2 = __ldg(&g_perm[e + 2]);
        int s3 = __ldg(&g_perm[e + 3]);
        float4 v0 = __ldg(&g[(size_t)s0 * 4 + q]);
        float4 v1 = __ldg(&g[(size_t)s1 * 4 + q]);
        float4 v2 = __ldg(&g[(size_t)s2 * 4 + q]);
        float4 v3 = __ldg(&g[(size_t)s3 * 4 + q]);
        acc = f4_add(acc, f4_add(f4_add(v0, v1), f4_add(v2, v3)));
    }
    for (; e < end; e++) {
        int s0 = __ldg(&g_perm[e]);
        acc = f4_add(acc, __ldg(&g[(size_t)s0 * 4 + q]));
    }
    return acc;
}

// reduce layer1 + fused: t = relu(dinv*acc + b1); h2 = t @ W2; g2 = h2*dinv
__global__ void __launch_bounds__(256) k_reduce1(const float* __restrict__ b1,
                                                 const float* __restrict__ W2, int N) {
    __shared__ float4 W2s[64];
    __shared__ float4 b1s[4];
    int t = threadIdx.x;
    if (t < 64) W2s[t] = ((const float4*)W2)[t];
    if (t < 4)  b1s[t] = ((const float4*)b1)[t];
    __syncthreads();

    int gid = blockIdx.x * 256 + t;
    int n = gid >> 2;
    int q = gid & 3;
    bool valid = (n < N);
    int nc = valid ? n : (N - 1);

    float4 acc = seg_sum(g_g1, nc, q);
    float di = g_dinv[nc];
    float4 o = f4_fma(di, acc, b1s[q]);
    float tv0 = fmaxf(o.x, 0.f), tv1 = fmaxf(o.y, 0.f);
    float tv2 = fmaxf(o.z, 0.f), tv3 = fmaxf(o.w, 0.f);

    float4 a = make_float4(0.f, 0.f, 0.f, 0.f);
    int lane = threadIdx.x & 31;
    int base = lane & ~3;
#pragma unroll
    for (int j = 0; j < 16; j++) {
        float src = (j & 3) == 0 ? tv0 : (j & 3) == 1 ? tv1 : (j & 3) == 2 ? tv2 : tv3;
        float tj = __shfl_sync(0xFFFFFFFFu, src, base + (j >> 2));
        a = f4_fma(tj, W2s[j * 4 + q], a);
    }
    if (valid) g_g2[(size_t)n * 4 + q] = f4_scale(a, di);
}

// reduce layer2 + fused mean-pool accumulate
__global__ void __launch_bounds__(256) k_reduce2(const void* __restrict__ batch,
                                                 const float* __restrict__ b2, int N) {
    int gid = blockIdx.x * blockDim.x + threadIdx.x;
    int n = gid >> 2;
    int q = gid & 3;
    if (n >= N) return;

    float4 acc = seg_sum(g_g2, n, q);
    float di = g_dinv[n];
    float4 y = f4_fma(di, acc, __ldg(&((const float4*)b2)[q]));

    int b = load_idx(batch, n, g_is32_b, NG);
    red_add_v4(&g_pool[b * 4 + q], y);
    if (q == 0) atomicAdd(&g_cnt[b], 1);
}

__global__ void __launch_bounds__(256) k_final(float* __restrict__ out) {
    int i = blockIdx.x * blockDim.x + threadIdx.x;
    if (i >= NG * 16) return;
    int g = i >> 4;
    float c = fmaxf((float)g_cnt[g], 1.0f);
    float s = ((const float*)g_pool)[i] / c;
    out[i] = 1.0f / (1.0f + expf(-s));
}

// ---------------- launch ----------------
// Aux stream + events created ONCE on the first (correctness, non-capture)
// call; during capture only launches + eventRecord/streamWaitEvent are issued
// (the documented capturable fork/join pattern). NonBlocking flag prevents
// implicit serialization with the legacy stream.
extern "C" void kernel_launch(void* const* d_in, const int* in_sizes, int n_in,
                              void* d_out, int out_size) {
    static cudaStream_t s_aux = nullptr;
    static cudaEvent_t  s_fork = nullptr, s_join = nullptr;
    static bool s_tried = false;
    if (!s_tried) {
        s_tried = true;
        if (cudaStreamCreateWithFlags(&s_aux, cudaStreamNonBlocking) != cudaSuccess)
            s_aux = nullptr;
        if (s_aux) {
            if (cudaEventCreateWithFlags(&s_fork, cudaEventDisableTiming) != cudaSuccess ||
                cudaEventCreateWithFlags(&s_join, cudaEventDisableTiming) != cudaSuccess)
                s_aux = nullptr;  // fall back to serial
        }
    }

    const float* x     = (const float*)d_in[0];
    const void*  ei    = d_in[1];               // [2, E] int32 OR int64 (probed)
    const void*  batch = d_in[2];               // [N]    int32 OR int64 (probed)
    const float* W1    = (const float*)d_in[3];
    const float* b1    = (const float*)d_in[4];
    const float* W2    = (const float*)d_in[5];
    const float* b2    = (const float*)d_in[6];
    float* out = (float*)d_out;

    int N = in_sizes[0] / 128;
    int E = in_sizes[1] / 2;

    int nb_nodes = (N + 255) / 256;
    int nb_edge4 = (E / 4 + 256) / 256;
    int nb_node4 = (4 * N + 255) / 256;

    k_init<<<nb_nodes, 256>>>(N);

    {
        int nsamp = E / 64;
        if (nsamp > 0)
            k_detect<0><<<(nsamp + 255) / 256, 256>>>((const unsigned*)ei, 0, nsamp, 64);
    }
    {
        long long off = (N > 4096) ? (long long)((N - 4096) & ~1) : 0;
        int nsamp = (int)((N - off) / 2);
        if (nsamp > 0)
            k_detect<1><<<(nsamp + 255) / 256, 256>>>((const unsigned*)batch, off, nsamp, 1);
    }

    // CSR build (deg -> scan -> dinv ready)
    k_deg<<<nb_edge4, 256>>>(ei, E, N);
    k_scan1<<<nb_nodes, 256>>>(N);
    k_scan2<<<1, 512>>>(nb_nodes);
    k_scan3<<<nb_nodes, 256>>>(N);

    int nb_g = (N + 511) / 512;
    if (s_aux) {
        // fork: gemm1 (needs only dinv) overlaps with k_place
        cudaEventRecord(s_fork, 0);
        cudaStreamWaitEvent(s_aux, s_fork, 0);
        k_gemm1<<<nb_g, 256, 0, s_aux>>>(x, W1, N);
        k_place<<<nb_edge4, 256>>>(ei, E, N);
        cudaEventRecord(s_join, s_aux);
        cudaStreamWaitEvent(0, s_join, 0);
    } else {
        k_place<<<nb_edge4, 256>>>(ei, E, N);
        k_gemm1<<<nb_g, 256>>>(x, W1, N);
    }

    k_reduce1<<<nb_node4, 256>>>(b1, W2, N);
    k_reduce2<<<nb_node4, 256>>>(batch, b2, N);
    k_final<<<(NG * 16 + 255) / 256, 256>>>(out);
}

// round 11
// speedup vs baseline: 1.1381x; 1.0496x over previous
#include <cuda_runtime.h>
#include <cuda_fp16.h>
#include <math.h>

#define MAXN 100000
#define MAXE 3200000
#define NG 256

// ---------------- device scratch (no allocations allowed) ----------------
__device__ int    g_is32_ei;            // 1 if edge_index is int32, 0 if int64
__device__ int    g_is32_b;             // 1 if batch is int32, 0 if int64
__device__ int    g_deg[MAXN];          // edge-only in-degree
__device__ int    g_rowp[MAXN];         // CSR row start (exclusive prefix of deg)
__device__ int    g_cursor[MAXN];       // placement cursors
__device__ int    g_bsum[512];          // block sums for 2-level scan
__device__ int    g_perm[MAXE];         // src node id, grouped by dst
__device__ float  g_dinv[MAXN];         // rsqrt(deg+1)
// fp16-packed pre-scaled features: element (n*4+q) holds features 4q..4q+3 as 4 halves
__device__ uint2  g_g1h[MAXN * 4];      // layer1 g1 = h1*dinv   [N,16] fp16
__device__ uint2  g_g2h[MAXN * 4];      // layer2 g2 = h2*dinv   [N,16] fp16
__device__ float4 g_pool[NG * 4];       // per-graph sums [256,16] fp32
__device__ int    g_cnt[NG];            // per-graph node counts

__device__ __forceinline__ void red_add_v4(float4* addr, float4 v) {
    asm volatile("red.global.add.v4.f32 [%0], {%1,%2,%3,%4};"
                 :: "l"(addr), "f"(v.x), "f"(v.y), "f"(v.z), "f"(v.w)
                 : "memory");
}
__device__ __forceinline__ float4 f4_fma(float s, float4 w, float4 a) {
    a.x = fmaf(s, w.x, a.x); a.y = fmaf(s, w.y, a.y);
    a.z = fmaf(s, w.z, a.z); a.w = fmaf(s, w.w, a.w);
    return a;
}
__device__ __forceinline__ float4 f4_scale(float4 a, float s) {
    return make_float4(a.x * s, a.y * s, a.z * s, a.w * s);
}
__device__ __forceinline__ float4 f4_add(float4 a, float4 b) {
    return make_float4(a.x + b.x, a.y + b.y, a.z + b.z, a.w + b.w);
}
__device__ __forceinline__ int clampi(int v, int hi) { return min(max(v, 0), hi - 1); }
__device__ __forceinline__ int load_idx(const void* p, long long i, int is32, int hi) {
    int v = is32 ? ((const int*)p)[i] : (int)((const long long*)p)[i];
    return clampi(v, hi);
}
// pack float4 -> 4 halves in a uint2
__device__ __forceinline__ uint2 f4_to_h4(float4 a) {
    __half2 p01 = __floats2half2_rn(a.x, a.y);
    __half2 p23 = __floats2half2_rn(a.z, a.w);
    uint2 u;
    u.x = *reinterpret_cast<unsigned*>(&p01);
    u.y = *reinterpret_cast<unsigned*>(&p23);
    return u;
}
// unpack + accumulate: acc += h4(v)
__device__ __forceinline__ float4 h4_acc(uint2 v, float4 acc) {
    __half2 p01 = *reinterpret_cast<__half2*>(&v.x);
    __half2 p23 = *reinterpret_cast<__half2*>(&v.y);
    float2 f01 = __half22float2(p01);
    float2 f23 = __half22float2(p23);
    acc.x += f01.x; acc.y += f01.y; acc.z += f23.x; acc.w += f23.y;
    return acc;
}

// ---------------- kernels ----------------

__global__ void __launch_bounds__(256) k_init(int N) {
    int i = blockIdx.x * blockDim.x + threadIdx.x;
    if (i < N)      g_deg[i] = 0;
    if (i < NG * 4) g_pool[i] = make_float4(0.f, 0.f, 0.f, 0.f);
    if (i < NG)     g_cnt[i]  = 0;
    if (i == 0) { g_is32_ei = 0; g_is32_b = 0; }
}

// dtype probe: odd dwords of int64 index data (< 2^31) are all zero.
template <int WHICH>
__global__ void __launch_bounds__(256) k_detect(const unsigned* __restrict__ buf,
                                                long long off, int nsamp, long long stride) {
    int k = blockIdx.x * blockDim.x + threadIdx.x;
    int v = 0;
    if (k < nsamp) v = (buf[off + 2LL * k * stride + 1] != 0u) ? 1 : 0;
    int any = __syncthreads_or(v);
    if (threadIdx.x == 0 && any) {
        if (WHICH == 0) atomicOr(&g_is32_ei, 1);
        else            atomicOr(&g_is32_b, 1);
    }
}

// degree count: 4 edges per thread (int4 fast path when E%4==0)
__global__ void __launch_bounds__(256) k_deg(const void* __restrict__ ei, int E, int N) {
    int t = blockIdx.x * blockDim.x + threadIdx.x;
    int e0 = t * 4;
    if (e0 >= E) return;
    if (g_is32_ei) {
        const int* dst = (const int*)ei + E;
        if ((E & 3) == 0) {
            int4 d4 = __ldg((const int4*)dst + t);
            atomicAdd(&g_deg[clampi(d4.x, N)], 1);
            atomicAdd(&g_deg[clampi(d4.y, N)], 1);
            atomicAdd(&g_deg[clampi(d4.z, N)], 1);
            atomicAdd(&g_deg[clampi(d4.w, N)], 1);
        } else {
            #pragma unroll
            for (int k = 0; k < 4; k++)
                if (e0 + k < E) atomicAdd(&g_deg[clampi(__ldg(dst + e0 + k), N)], 1);
        }
    } else {
        const long long* dst = (const long long*)ei + E;
        #pragma unroll
        for (int k = 0; k < 4; k++)
            if (e0 + k < E) atomicAdd(&g_deg[clampi((int)__ldg(dst + e0 + k), N)], 1);
    }
}

// 2-level exclusive scan of g_deg -> g_rowp
__global__ void __launch_bounds__(256) k_scan1(int N) {
    __shared__ int sh[256];
    int t = threadIdx.x;
    int i = blockIdx.x * 256 + t;
    int v = (i < N) ? g_deg[i] : 0;
    sh[t] = v;
    __syncthreads();
    for (int off = 1; off < 256; off <<= 1) {
        int add = (t >= off) ? sh[t - off] : 0;
        __syncthreads();
        sh[t] += add;
        __syncthreads();
    }
    if (i < N) g_rowp[i] = sh[t] - v;
    if (t == 255) g_bsum[blockIdx.x] = sh[255];
}

__global__ void __launch_bounds__(512) k_scan2(int nb) {
    __shared__ int sh[512];
    int t = threadIdx.x;
    int v = (t < nb) ? g_bsum[t] : 0;
    sh[t] = v;
    __syncthreads();
    for (int off = 1; off < 512; off <<= 1) {
        int add = (t >= off) ? sh[t - off] : 0;
        __syncthreads();
        sh[t] += add;
        __syncthreads();
    }
    if (t < nb) g_bsum[t] = sh[t] - v;
}

__global__ void __launch_bounds__(256) k_scan3(int N) {
    int i = blockIdx.x * blockDim.x + threadIdx.x;
    if (i >= N) return;
    int r = g_rowp[i] + g_bsum[i >> 8];
    g_rowp[i]   = r;
    g_cursor[i] = r;
    g_dinv[i]   = rsqrtf((float)(g_deg[i] + 1));  // +1 self loop
}

// place src ids grouped by dst: 4 edges/thread
__global__ void __launch_bounds__(256) k_place(const void* __restrict__ ei, int E, int N) {
    int t = blockIdx.x * blockDim.x + threadIdx.x;
    int e0 = t * 4;
    if (e0 >= E) return;
    if (g_is32_ei) {
        const int* src = (const int*)ei;
        const int* dst = src + E;
        if ((E & 3) == 0) {
            int4 s4 = __ldg((const int4*)src + t);
            int4 d4 = __ldg((const int4*)dst + t);
            g_perm[atomicAdd(&g_cursor[clampi(d4.x, N)], 1)] = clampi(s4.x, N);
            g_perm[atomicAdd(&g_cursor[clampi(d4.y, N)], 1)] = clampi(s4.y, N);
            g_perm[atomicAdd(&g_cursor[clampi(d4.z, N)], 1)] = clampi(s4.z, N);
            g_perm[atomicAdd(&g_cursor[clampi(d4.w, N)], 1)] = clampi(s4.w, N);
        } else {
            #pragma unroll
            for (int k = 0; k < 4; k++)
                if (e0 + k < E) {
                    int s = clampi(__ldg(src + e0 + k), N);
                    int d = clampi(__ldg(dst + e0 + k), N);
                    g_perm[atomicAdd(&g_cursor[d], 1)] = s;
                }
        }
    } else {
        const long long* src = (const long long*)ei;
        const long long* dst = src + E;
        #pragma unroll
        for (int k = 0; k < 4; k++)
            if (e0 + k < E) {
                int s = clampi((int)__ldg(src + e0 + k), N);
                int d = clampi((int)__ldg(dst + e0 + k), N);
                g_perm[atomicAdd(&g_cursor[d], 1)] = s;
            }
    }
}

// g1 = (x @ W1) * dinv  (fp32 compute, fp16 store); 2 nodes/thread
__global__ void __launch_bounds__(256) k_gemm1(const float* __restrict__ x,
                                               const float* __restrict__ W1, int N) {
    __shared__ float4 Ws[512];   // W1 as [128 rows][4 float4-cols]
    int t = threadIdx.x;
    Ws[t]       = ((const float4*)W1)[t];
    Ws[t + 256] = ((const float4*)W1)[t + 256];
    __syncthreads();

    int n0 = blockIdx.x * 512 + t;
    int n1 = n0 + 256;
    bool v0 = (n0 < N), v1 = (n1 < N);
    if (!v0) return;

    float4 a0 = make_float4(0.f, 0.f, 0.f, 0.f);
    float4 a1 = a0, a2 = a0, a3 = a0;
    float4 c0 = a0, c1 = a0, c2 = a0, c3 = a0;
    const float4* xr0 = (const float4*)(x + (size_t)n0 * 128);
    const float4* xr1 = (const float4*)(x + (size_t)(v1 ? n1 : n0) * 128);

#pragma unroll 2
    for (int k4 = 0; k4 < 32; k4++) {
        float4 xa = __ldg(&xr0[k4]);
        float4 xb = __ldg(&xr1[k4]);
        const float4* w = &Ws[(k4 * 4) * 4];
#pragma unroll
        for (int j = 0; j < 4; j++) {
            float sa = (j == 0) ? xa.x : (j == 1) ? xa.y : (j == 2) ? xa.z : xa.w;
            float sb = (j == 0) ? xb.x : (j == 1) ? xb.y : (j == 2) ? xb.z : xb.w;
            float4 w0 = w[j * 4 + 0], w1 = w[j * 4 + 1], w2 = w[j * 4 + 2], w3 = w[j * 4 + 3];
            a0 = f4_fma(sa, w0, a0); a1 = f4_fma(sa, w1, a1);
            a2 = f4_fma(sa, w2, a2); a3 = f4_fma(sa, w3, a3);
            c0 = f4_fma(sb, w0, c0); c1 = f4_fma(sb, w1, c1);
            c2 = f4_fma(sb, w2, c2); c3 = f4_fma(sb, w3, c3);
        }
    }

    float d0 = g_dinv[n0];
    g_g1h[n0 * 4 + 0] = f4_to_h4(f4_scale(a0, d0));
    g_g1h[n0 * 4 + 1] = f4_to_h4(f4_scale(a1, d0));
    g_g1h[n0 * 4 + 2] = f4_to_h4(f4_scale(a2, d0));
    g_g1h[n0 * 4 + 3] = f4_to_h4(f4_scale(a3, d0));
    if (v1) {
        float d1 = g_dinv[n1];
        g_g1h[n1 * 4 + 0] = f4_to_h4(f4_scale(c0, d1));
        g_g1h[n1 * 4 + 1] = f4_to_h4(f4_scale(c1, d1));
        g_g1h[n1 * 4 + 2] = f4_to_h4(f4_scale(c2, d1));
        g_g1h[n1 * 4 + 3] = f4_to_h4(f4_scale(c3, d1));
    }
}

// segmented fp16 gather-sum over incoming edges, seeded with self-loop g[n].
// Unrolled by 8 for gather MLP (avg degree ~33); fp32 accumulation.
__device__ __forceinline__ float4 seg_sum_h(const uint2* __restrict__ g, int n, int q) {
    int start = g_rowp[n];
    int end   = start + g_deg[n];
    float4 acc = make_float4(0.f, 0.f, 0.f, 0.f);
    acc = h4_acc(__ldg(&g[(size_t)n * 4 + q]), acc);   // self loop
    int e = start;
    for (; e + 8 <= end; e += 8) {
        int s[8]; uint2 v[8];
#pragma unroll
        for (int k = 0; k < 8; k++) s[k] = __ldg(&g_perm[e + k]);
#pragma unroll
        for (int k = 0; k < 8; k++) v[k] = __ldg(&g[(size_t)s[k] * 4 + q]);
#pragma unroll
        for (int k = 0; k < 8; k++) acc = h4_acc(v[k], acc);
    }
    for (; e < end; e++) {
        int s0 = __ldg(&g_perm[e]);
        acc = h4_acc(__ldg(&g[(size_t)s0 * 4 + q]), acc);
    }
    return acc;
}

// reduce layer1 + fused: t = relu(dinv*acc + b1); h2 = t @ W2; g2 = h2*dinv (fp16)
__global__ void __launch_bounds__(256) k_reduce1(const float* __restrict__ b1,
                                                 const float* __restrict__ W2, int N) {
    __shared__ float4 W2s[64];
    __shared__ float4 b1s[4];
    int t = threadIdx.x;
    if (t < 64) W2s[t] = ((const float4*)W2)[t];
    if (t < 4)  b1s[t] = ((const float4*)b1)[t];
    __syncthreads();

    int gid = blockIdx.x * 256 + t;
    int n = gid >> 2;
    int q = gid & 3;
    bool valid = (n < N);
    int nc = valid ? n : (N - 1);

    float4 acc = seg_sum_h(g_g1h, nc, q);
    float di = g_dinv[nc];
    float4 o = f4_fma(di, acc, b1s[q]);
    float tv0 = fmaxf(o.x, 0.f), tv1 = fmaxf(o.y, 0.f);
    float tv2 = fmaxf(o.z, 0.f), tv3 = fmaxf(o.w, 0.f);

    float4 a = make_float4(0.f, 0.f, 0.f, 0.f);
    int lane = threadIdx.x & 31;
    int base = lane & ~3;
#pragma unroll
    for (int j = 0; j < 16; j++) {
        float src = (j & 3) == 0 ? tv0 : (j & 3) == 1 ? tv1 : (j & 3) == 2 ? tv2 : tv3;
        float tj = __shfl_sync(0xFFFFFFFFu, src, base + (j >> 2));
        a = f4_fma(tj, W2s[j * 4 + q], a);
    }
    if (valid) g_g2h[(size_t)n * 4 + q] = f4_to_h4(f4_scale(a, di));
}

// reduce layer2 + fused mean-pool accumulate (fp32 pool)
__global__ void __launch_bounds__(256) k_reduce2(const void* __restrict__ batch,
                                                 const float* __restrict__ b2, int N) {
    int gid = blockIdx.x * blockDim.x + threadIdx.x;
    int n = gid >> 2;
    int q = gid & 3;
    if (n >= N) return;

    float4 acc = seg_sum_h(g_g2h, n, q);
    float di = g_dinv[n];
    float4 y = f4_fma(di, acc, __ldg(&((const float4*)b2)[q]));

    int b = load_idx(batch, n, g_is32_b, NG);
    red_add_v4(&g_pool[b * 4 + q], y);
    if (q == 0) atomicAdd(&g_cnt[b], 1);
}

__global__ void __launch_bounds__(256) k_final(float* __restrict__ out) {
    int i = blockIdx.x * blockDim.x + threadIdx.x;
    if (i >= NG * 16) return;
    int g = i >> 4;
    float c = fmaxf((float)g_cnt[g], 1.0f);
    float s = ((const float*)g_pool)[i] / c;
    out[i] = 1.0f / (1.0f + expf(-s));
}

// ---------------- launch ----------------
// Aux stream + events created ONCE on the first (correctness, non-capture)
// call; during capture only launches + eventRecord/streamWaitEvent are issued
// (the documented capturable fork/join pattern).
extern "C" void kernel_launch(void* const* d_in, const int* in_sizes, int n_in,
                              void* d_out, int out_size) {
    static cudaStream_t s_aux = nullptr;
    static cudaEvent_t  s_fork = nullptr, s_join = nullptr;
    static bool s_tried = false;
    if (!s_tried) {
        s_tried = true;
        if (cudaStreamCreateWithFlags(&s_aux, cudaStreamNonBlocking) != cudaSuccess)
            s_aux = nullptr;
        if (s_aux) {
            if (cudaEventCreateWithFlags(&s_fork, cudaEventDisableTiming) != cudaSuccess ||
                cudaEventCreateWithFlags(&s_join, cudaEventDisableTiming) != cudaSuccess)
                s_aux = nullptr;  // fall back to serial
        }
    }

    const float* x     = (const float*)d_in[0];
    const void*  ei    = d_in[1];               // [2, E] int32 OR int64 (probed)
    const void*  batch = d_in[2];               // [N]    int32 OR int64 (probed)
    const float* W1    = (const float*)d_in[3];
    const float* b1    = (const float*)d_in[4];
    const float* W2    = (const float*)d_in[5];
    const float* b2    = (const float*)d_in[6];
    float* out = (float*)d_out;

    int N = in_sizes[0] / 128;
    int E = in_sizes[1] / 2;

    int nb_nodes = (N + 255) / 256;
    int nb_edge4 = (E / 4 + 256) / 256;
    int nb_node4 = (4 * N + 255) / 256;

    k_init<<<nb_nodes, 256>>>(N);

    {
        int nsamp = E / 64;
        if (nsamp > 0)
            k_detect<0><<<(nsamp + 255) / 256, 256>>>((const unsigned*)ei, 0, nsamp, 64);
    }
    {
        long long off = (N > 4096) ? (long long)((N - 4096) & ~1) : 0;
        int nsamp = (int)((N - off) / 2);
        if (nsamp > 0)
            k_detect<1><<<(nsamp + 255) / 256, 256>>>((const unsigned*)batch, off, nsamp, 1);
    }

    // CSR build (deg -> scan -> dinv ready)
    k_deg<<<nb_edge4, 256>>>(ei, E, N);
    k_scan1<<<nb_nodes, 256>>>(N);
    k_scan2<<<1, 512>>>(nb_nodes);
    k_scan3<<<nb_nodes, 256>>>(N);

    int nb_g = (N + 511) / 512;
    if (s_aux) {
        // fork: gemm1 (needs only dinv) overlaps with k_place
        cudaEventRecord(s_fork, 0);
        cudaStreamWaitEvent(s_aux, s_fork, 0);
        k_gemm1<<<nb_g, 256, 0, s_aux>>>(x, W1, N);
        k_place<<<nb_edge4, 256>>>(ei, E, N);
        cudaEventRecord(s_join, s_aux);
        cudaStreamWaitEvent(0, s_join, 0);
    } else {
        k_place<<<nb_edge4, 256>>>(ei, E, N);
        k_gemm1<<<nb_g, 256>>>(x, W1, N);
    }

    k_reduce1<<<nb_node4, 256>>>(b1, W2, N);
    k_reduce2<<<nb_node4, 256>>>(batch, b2, N);
    k_final<<<(NG * 16 + 255) / 256, 256>>>(out);
}

// round 12
// speedup vs baseline: 1.2020x; 1.0561x over previous
#include <cuda_runtime.h>
#include <cuda_fp16.h>
#include <math.h>

#define MAXN 100000
#define MAXE 3200000
#define MAXSLOTS (MAXE * 4)   // bucket table capacity (12.8M ints = 51.2 MB)
#define NG 256

// ---------------- device scratch (no allocations allowed) ----------------
__device__ int    g_is32_ei;            // 1 if edge_index is int32, 0 if int64
__device__ int    g_is32_b;             // 1 if batch is int32, 0 if int64
__device__ int    g_cursor[MAXN];       // per-dst fill cursor (== degree after place)
__device__ int    g_slots[MAXSLOTS];    // bucket table: src ids at d*stride + k
__device__ float  g_dinv[MAXN];         // rsqrt(deg+1)
// fp16-packed pre-scaled features: element (n*4+q) holds features 4q..4q+3 as 4 halves
__device__ uint2  g_g1h[MAXN * 4];      // layer1 g1 = h1*dinv   [N,16] fp16
__device__ uint2  g_g2h[MAXN * 4];      // layer2 g2 = h2*dinv   [N,16] fp16
__device__ float4 g_pool[NG * 4];       // per-graph sums [256,16] fp32
__device__ int    g_cnt[NG];            // per-graph node counts

__device__ __forceinline__ void red_add_v4(float4* addr, float4 v) {
    asm volatile("red.global.add.v4.f32 [%0], {%1,%2,%3,%4};"
                 :: "l"(addr), "f"(v.x), "f"(v.y), "f"(v.z), "f"(v.w)
                 : "memory");
}
__device__ __forceinline__ float4 f4_fma(float s, float4 w, float4 a) {
    a.x = fmaf(s, w.x, a.x); a.y = fmaf(s, w.y, a.y);
    a.z = fmaf(s, w.z, a.z); a.w = fmaf(s, w.w, a.w);
    return a;
}
__device__ __forceinline__ float4 f4_scale(float4 a, float s) {
    return make_float4(a.x * s, a.y * s, a.z * s, a.w * s);
}
__device__ __forceinline__ int clampi(int v, int hi) { return min(max(v, 0), hi - 1); }
__device__ __forceinline__ int load_idx(const void* p, long long i, int is32, int hi) {
    int v = is32 ? ((const int*)p)[i] : (int)((const long long*)p)[i];
    return clampi(v, hi);
}
__device__ __forceinline__ uint2 f4_to_h4(float4 a) {
    __half2 p01 = __floats2half2_rn(a.x, a.y);
    __half2 p23 = __floats2half2_rn(a.z, a.w);
    uint2 u;
    u.x = *reinterpret_cast<unsigned*>(&p01);
    u.y = *reinterpret_cast<unsigned*>(&p23);
    return u;
}
__device__ __forceinline__ float4 h4_to_f4(uint2 v) {
    __half2 p01 = *reinterpret_cast<__half2*>(&v.x);
    __half2 p23 = *reinterpret_cast<__half2*>(&v.y);
    float2 f01 = __half22float2(p01);
    float2 f23 = __half22float2(p23);
    return make_float4(f01.x, f01.y, f23.x, f23.y);
}
__device__ __forceinline__ float4 h4_acc(uint2 v, float4 acc) {
    float4 f = h4_to_f4(v);
    acc.x += f.x; acc.y += f.y; acc.z += f.z; acc.w += f.w;
    return acc;
}

// ---------------- kernels ----------------

__global__ void __launch_bounds__(256) k_init(int N) {
    int i = blockIdx.x * blockDim.x + threadIdx.x;
    if (i < N)      g_cursor[i] = 0;
    if (i < NG * 4) g_pool[i] = make_float4(0.f, 0.f, 0.f, 0.f);
    if (i < NG)     g_cnt[i]  = 0;
    if (i == 0) { g_is32_ei = 0; g_is32_b = 0; }
}

// dtype probe: odd dwords of int64 index data (< 2^31) are all zero.
template <int WHICH>
__global__ void __launch_bounds__(256) k_detect(const unsigned* __restrict__ buf,
                                                long long off, int nsamp, long long stride) {
    int k = blockIdx.x * blockDim.x + threadIdx.x;
    int v = 0;
    if (k < nsamp) v = (buf[off + 2LL * k * stride + 1] != 0u) ? 1 : 0;
    int any = __syncthreads_or(v);
    if (threadIdx.x == 0 && any) {
        if (WHICH == 0) atomicOr(&g_is32_ei, 1);
        else            atomicOr(&g_is32_b, 1);
    }
}

// direct bucket placement: slots[d*stride + cursor[d]++] = s  (4 edges/thread)
__global__ void __launch_bounds__(256) k_place(const void* __restrict__ ei, int E, int N,
                                               int stride) {
    int t = blockIdx.x * blockDim.x + threadIdx.x;
    int e0 = t * 4;
    if (e0 >= E) return;
    if (g_is32_ei) {
        const int* src = (const int*)ei;
        const int* dst = src + E;
        if ((E & 3) == 0) {
            int4 s4 = __ldg((const int4*)src + t);
            int4 d4 = __ldg((const int4*)dst + t);
            int d, k;
            d = clampi(d4.x, N); k = atomicAdd(&g_cursor[d], 1);
            if (k < stride) g_slots[d * stride + k] = clampi(s4.x, N);
            d = clampi(d4.y, N); k = atomicAdd(&g_cursor[d], 1);
            if (k < stride) g_slots[d * stride + k] = clampi(s4.y, N);
            d = clampi(d4.z, N); k = atomicAdd(&g_cursor[d], 1);
            if (k < stride) g_slots[d * stride + k] = clampi(s4.z, N);
            d = clampi(d4.w, N); k = atomicAdd(&g_cursor[d], 1);
            if (k < stride) g_slots[d * stride + k] = clampi(s4.w, N);
        } else {
            #pragma unroll
            for (int j = 0; j < 4; j++)
                if (e0 + j < E) {
                    int s = clampi(__ldg(src + e0 + j), N);
                    int d = clampi(__ldg(dst + e0 + j), N);
                    int k = atomicAdd(&g_cursor[d], 1);
                    if (k < stride) g_slots[d * stride + k] = s;
                }
        }
    } else {
        const long long* src = (const long long*)ei;
        const long long* dst = src + E;
        #pragma unroll
        for (int j = 0; j < 4; j++)
            if (e0 + j < E) {
                int s = clampi((int)__ldg(src + e0 + j), N);
                int d = clampi((int)__ldg(dst + e0 + j), N);
                int k = atomicAdd(&g_cursor[d], 1);
                if (k < stride) g_slots[d * stride + k] = s;
            }
    }
}

// h1 = x @ W1, stored UNSCALED as fp16 (dinv applied later) — zero dependencies.
// 2 nodes per thread to reuse W smem loads.
__global__ void __launch_bounds__(256) k_gemm1(const float* __restrict__ x,
                                               const float* __restrict__ W1, int N) {
    __shared__ float4 Ws[512];   // W1 as [128 rows][4 float4-cols]
    int t = threadIdx.x;
    Ws[t]       = ((const float4*)W1)[t];
    Ws[t + 256] = ((const float4*)W1)[t + 256];
    __syncthreads();

    int n0 = blockIdx.x * 512 + t;
    int n1 = n0 + 256;
    bool v0 = (n0 < N), v1 = (n1 < N);
    if (!v0) return;

    float4 a0 = make_float4(0.f, 0.f, 0.f, 0.f);
    float4 a1 = a0, a2 = a0, a3 = a0;
    float4 c0 = a0, c1 = a0, c2 = a0, c3 = a0;
    const float4* xr0 = (const float4*)(x + (size_t)n0 * 128);
    const float4* xr1 = (const float4*)(x + (size_t)(v1 ? n1 : n0) * 128);

#pragma unroll 2
    for (int k4 = 0; k4 < 32; k4++) {
        float4 xa = __ldg(&xr0[k4]);
        float4 xb = __ldg(&xr1[k4]);
        const float4* w = &Ws[(k4 * 4) * 4];
#pragma unroll
        for (int j = 0; j < 4; j++) {
            float sa = (j == 0) ? xa.x : (j == 1) ? xa.y : (j == 2) ? xa.z : xa.w;
            float sb = (j == 0) ? xb.x : (j == 1) ? xb.y : (j == 2) ? xb.z : xb.w;
            float4 w0 = w[j * 4 + 0], w1 = w[j * 4 + 1], w2 = w[j * 4 + 2], w3 = w[j * 4 + 3];
            a0 = f4_fma(sa, w0, a0); a1 = f4_fma(sa, w1, a1);
            a2 = f4_fma(sa, w2, a2); a3 = f4_fma(sa, w3, a3);
            c0 = f4_fma(sb, w0, c0); c1 = f4_fma(sb, w1, c1);
            c2 = f4_fma(sb, w2, c2); c3 = f4_fma(sb, w3, c3);
        }
    }

    g_g1h[n0 * 4 + 0] = f4_to_h4(a0); g_g1h[n0 * 4 + 1] = f4_to_h4(a1);
    g_g1h[n0 * 4 + 2] = f4_to_h4(a2); g_g1h[n0 * 4 + 3] = f4_to_h4(a3);
    if (v1) {
        g_g1h[n1 * 4 + 0] = f4_to_h4(c0); g_g1h[n1 * 4 + 1] = f4_to_h4(c1);
        g_g1h[n1 * 4 + 2] = f4_to_h4(c2); g_g1h[n1 * 4 + 3] = f4_to_h4(c3);
    }
}

// after place+gemm1: dinv from cursor; scale g1h rows by dinv in place
__global__ void __launch_bounds__(256) k_dinv_scale(int N, int stride) {
    int gid = blockIdx.x * blockDim.x + threadIdx.x;
    int n = gid >> 2;
    int q = gid & 3;
    if (n >= N) return;
    int deg = min(g_cursor[n], stride);
    float di = rsqrtf((float)(deg + 1));
    if (q == 0) g_dinv[n] = di;
    size_t idx = (size_t)n * 4 + q;
    g_g1h[idx] = f4_to_h4(f4_scale(h4_to_f4(g_g1h[idx]), di));
}

// segmented fp16 gather-sum over bucket row, seeded with self-loop g[n]
__device__ __forceinline__ float4 seg_sum_h(const uint2* __restrict__ g, int n, int q,
                                            int stride) {
    int deg   = min(g_cursor[n], stride);
    int start = n * stride;
    int end   = start + deg;
    float4 acc = make_float4(0.f, 0.f, 0.f, 0.f);
    acc = h4_acc(__ldg(&g[(size_t)n * 4 + q]), acc);   // self loop
    int e = start;
    for (; e + 8 <= end; e += 8) {
        int s[8]; uint2 v[8];
#pragma unroll
        for (int k = 0; k < 8; k++) s[k] = __ldg(&g_slots[e + k]);
#pragma unroll
        for (int k = 0; k < 8; k++) v[k] = __ldg(&g[(size_t)s[k] * 4 + q]);
#pragma unroll
        for (int k = 0; k < 8; k++) acc = h4_acc(v[k], acc);
    }
    for (; e < end; e++) {
        int s0 = __ldg(&g_slots[e]);
        acc = h4_acc(__ldg(&g[(size_t)s0 * 4 + q]), acc);
    }
    return acc;
}

// reduce layer1 + fused: t = relu(dinv*acc + b1); h2 = t @ W2; g2 = h2*dinv (fp16)
__global__ void __launch_bounds__(256) k_reduce1(const float* __restrict__ b1,
                                                 const float* __restrict__ W2, int N,
                                                 int stride) {
    __shared__ float4 W2s[64];
    __shared__ float4 b1s[4];
    int t = threadIdx.x;
    if (t < 64) W2s[t] = ((const float4*)W2)[t];
    if (t < 4)  b1s[t] = ((const float4*)b1)[t];
    __syncthreads();

    int gid = blockIdx.x * 256 + t;
    int n = gid >> 2;
    int q = gid & 3;
    bool valid = (n < N);
    int nc = valid ? n : (N - 1);

    float4 acc = seg_sum_h(g_g1h, nc, q, stride);
    float di = g_dinv[nc];
    float4 o = f4_fma(di, acc, b1s[q]);
    float tv0 = fmaxf(o.x, 0.f), tv1 = fmaxf(o.y, 0.f);
    float tv2 = fmaxf(o.z, 0.f), tv3 = fmaxf(o.w, 0.f);

    float4 a = make_float4(0.f, 0.f, 0.f, 0.f);
    int lane = threadIdx.x & 31;
    int base = lane & ~3;
#pragma unroll
    for (int j = 0; j < 16; j++) {
        float src = (j & 3) == 0 ? tv0 : (j & 3) == 1 ? tv1 : (j & 3) == 2 ? tv2 : tv3;
        float tj = __shfl_sync(0xFFFFFFFFu, src, base + (j >> 2));
        a = f4_fma(tj, W2s[j * 4 + q], a);
    }
    if (valid) g_g2h[(size_t)n * 4 + q] = f4_to_h4(f4_scale(a, di));
}

// reduce layer2 + fused mean-pool accumulate (fp32 pool)
__global__ void __launch_bounds__(256) k_reduce2(const void* __restrict__ batch,
                                                 const float* __restrict__ b2, int N,
                                                 int stride) {
    int gid = blockIdx.x * blockDim.x + threadIdx.x;
    int n = gid >> 2;
    int q = gid & 3;
    if (n >= N) return;

    float4 acc = seg_sum_h(g_g2h, n, q, stride);
    float di = g_dinv[n];
    float4 y = f4_fma(di, acc, __ldg(&((const float4*)b2)[q]));

    int b = load_idx(batch, n, g_is32_b, NG);
    red_add_v4(&g_pool[b * 4 + q], y);
    if (q == 0) atomicAdd(&g_cnt[b], 1);
}

__global__ void __launch_bounds__(256) k_final(float* __restrict__ out) {
    int i = blockIdx.x * blockDim.x + threadIdx.x;
    if (i >= NG * 16) return;
    int g = i >> 4;
    float c = fmaxf((float)g_cnt[g], 1.0f);
    float s = ((const float*)g_pool)[i] / c;
    out[i] = 1.0f / (1.0f + expf(-s));
}

// ---------------- launch ----------------
// gemm1 has NO dependencies -> forked at graph start on the aux stream,
// fully hidden under init+detect+place. Stream/events created once on the
// first (non-capture) call; capture sees only launches + event edges.
extern "C" void kernel_launch(void* const* d_in, const int* in_sizes, int n_in,
                              void* d_out, int out_size) {
    static cudaStream_t s_aux = nullptr;
    static cudaEvent_t  s_fork = nullptr, s_join = nullptr;
    static bool s_tried = false;
    if (!s_tried) {
        s_tried = true;
        if (cudaStreamCreateWithFlags(&s_aux, cudaStreamNonBlocking) != cudaSuccess)
            s_aux = nullptr;
        if (s_aux) {
            if (cudaEventCreateWithFlags(&s_fork, cudaEventDisableTiming) != cudaSuccess ||
                cudaEventCreateWithFlags(&s_join, cudaEventDisableTiming) != cudaSuccess)
                s_aux = nullptr;
        }
    }

    const float* x     = (const float*)d_in[0];
    const void*  ei    = d_in[1];               // [2, E] int32 OR int64 (probed)
    const void*  batch = d_in[2];               // [N]    int32 OR int64 (probed)
    const float* W1    = (const float*)d_in[3];
    const float* b1    = (const float*)d_in[4];
    const float* W2    = (const float*)d_in[5];
    const float* b2    = (const float*)d_in[6];
    float* out = (float*)d_out;

    int N = in_sizes[0] / 128;
    int E = in_sizes[1] / 2;

    // bucket stride: pow2-ish headroom over mean degree, capped by capacity
    int stride = 128;
    while ((long long)stride * N > MAXSLOTS && stride > 8) stride >>= 1;

    int nb_nodes = (N + 255) / 256;
    int nb_edge4 = (E / 4 + 256) / 256;
    int nb_node4 = (4 * N + 255) / 256;
    int nb_g     = (N + 511) / 512;

    if (s_aux) {
        cudaEventRecord(s_fork, 0);
        cudaStreamWaitEvent(s_aux, s_fork, 0);
        k_gemm1<<<nb_g, 256, 0, s_aux>>>(x, W1, N);   // independent: overlaps everything below
    }

    k_init<<<nb_nodes, 256>>>(N);
    {
        int nsamp = E / 64;
        if (nsamp > 0)
            k_detect<0><<<(nsamp + 255) / 256, 256>>>((const unsigned*)ei, 0, nsamp, 64);
    }
    {
        long long off = (N > 4096) ? (long long)((N - 4096) & ~1) : 0;
        int nsamp = (int)((N - off) / 2);
        if (nsamp > 0)
            k_detect<1><<<(nsamp + 255) / 256, 256>>>((const unsigned*)batch, off, nsamp, 1);
    }
    k_place<<<nb_edge4, 256>>>(ei, E, N, stride);

    if (s_aux) {
        cudaEventRecord(s_join, s_aux);
        cudaStreamWaitEvent(0, s_join, 0);
    } else {
        k_gemm1<<<nb_g, 256>>>(x, W1, N);
    }

    k_dinv_scale<<<nb_node4, 256>>>(N, stride);
    k_reduce1<<<nb_node4, 256>>>(b1, W2, N, stride);
    k_reduce2<<<nb_node4, 256>>>(batch, b2, N, stride);
    k_final<<<(NG * 16 + 255) / 256, 256>>>(out);
}

// round 13
// speedup vs baseline: 1.2834x; 1.0677x over previous
#include <cuda_runtime.h>
#include <cuda_fp16.h>
#include <math.h>

#define MAXN 100000
#define MAXE 3200000
#define MAXSLOTS (MAXE * 4)   // bucket table capacity (12.8M ints = 51.2 MB)
#define NG 256

// ---------------- device scratch (no allocations allowed) ----------------
__device__ int    g_is32_ei;            // 1 if edge_index is int32, 0 if int64
__device__ int    g_is32_b;             // 1 if batch is int32, 0 if int64
__device__ int    g_cursor[MAXN];       // per-dst fill cursor (== degree after place)
__device__ int    g_slots[MAXSLOTS];    // bucket table: src ids at d*stride + k
__device__ float  g_dinv[MAXN];         // rsqrt(deg+1)
// fp16-packed features, [N,16] as N*4 uint2 (quad q holds features 4q..4q+3)
__device__ uint2  g_g1h[MAXN * 4];      // layer1 g1 = h1*dinv
__device__ uint2  g_g2h[MAXN * 4];      // layer2 g2 = h2*dinv
__device__ float4 g_pool[NG * 4];       // per-graph sums [256,16] fp32
__device__ int    g_cnt[NG];            // per-graph node counts

__device__ __forceinline__ void red_add_v4(float4* addr, float4 v) {
    asm volatile("red.global.add.v4.f32 [%0], {%1,%2,%3,%4};"
                 :: "l"(addr), "f"(v.x), "f"(v.y), "f"(v.z), "f"(v.w)
                 : "memory");
}
__device__ __forceinline__ float4 f4_fma(float s, float4 w, float4 a) {
    a.x = fmaf(s, w.x, a.x); a.y = fmaf(s, w.y, a.y);
    a.z = fmaf(s, w.z, a.z); a.w = fmaf(s, w.w, a.w);
    return a;
}
__device__ __forceinline__ float4 f4_scale(float4 a, float s) {
    return make_float4(a.x * s, a.y * s, a.z * s, a.w * s);
}
__device__ __forceinline__ int clampi(int v, int hi) { return min(max(v, 0), hi - 1); }
__device__ __forceinline__ int load_idx(const void* p, long long i, int is32, int hi) {
    int v = is32 ? ((const int*)p)[i] : (int)((const long long*)p)[i];
    return clampi(v, hi);
}
__device__ __forceinline__ uint2 f4_to_h4(float4 a) {
    __half2 p01 = __floats2half2_rn(a.x, a.y);
    __half2 p23 = __floats2half2_rn(a.z, a.w);
    uint2 u;
    u.x = *reinterpret_cast<unsigned*>(&p01);
    u.y = *reinterpret_cast<unsigned*>(&p23);
    return u;
}
__device__ __forceinline__ float4 h4_to_f4(uint2 v) {
    __half2 p01 = *reinterpret_cast<__half2*>(&v.x);
    __half2 p23 = *reinterpret_cast<__half2*>(&v.y);
    float2 f01 = __half22float2(p01);
    float2 f23 = __half22float2(p23);
    return make_float4(f01.x, f01.y, f23.x, f23.y);
}
__device__ __forceinline__ __half2 u2h(unsigned u) { return *reinterpret_cast<__half2*>(&u); }

// ---------------- kernels ----------------

__global__ void __launch_bounds__(256) k_init(int N) {
    int i = blockIdx.x * blockDim.x + threadIdx.x;
    if (i < N)      g_cursor[i] = 0;
    if (i < NG * 4) g_pool[i] = make_float4(0.f, 0.f, 0.f, 0.f);
    if (i < NG)     g_cnt[i]  = 0;
    if (i == 0) { g_is32_ei = 0; g_is32_b = 0; }
}

// merged dtype probe: blocks 0..7 sample edge_index, block 8 samples batch tail.
// int64 index data (< 2^31) has all-zero odd dwords.
__global__ void __launch_bounds__(256) k_detect_all(const unsigned* __restrict__ ei,
                                                    long long strideE, int nsampE,
                                                    const unsigned* __restrict__ batch,
                                                    long long offB, int nsampB) {
    int t = threadIdx.x;
    int v = 0;
    if (blockIdx.x < 8) {
        int k = blockIdx.x * 256 + t;
        if (k < nsampE) v = (ei[2LL * k * strideE + 1] != 0u) ? 1 : 0;
        int any = __syncthreads_or(v);
        if (t == 0 && any) atomicOr(&g_is32_ei, 1);
    } else {
        int k = t;
        if (k < nsampB) v = (batch[offB + 2LL * k + 1] != 0u) ? 1 : 0;
        int any = __syncthreads_or(v);
        if (t == 0 && any) atomicOr(&g_is32_b, 1);
    }
}

// direct bucket placement: slots[d*stride + cursor[d]++] = s  (4 edges/thread)
__global__ void __launch_bounds__(256) k_place(const void* __restrict__ ei, int E, int N,
                                               int stride) {
    int t = blockIdx.x * blockDim.x + threadIdx.x;
    int e0 = t * 4;
    if (e0 >= E) return;
    if (g_is32_ei) {
        const int* src = (const int*)ei;
        const int* dst = src + E;
        if ((E & 3) == 0) {
            int4 s4 = __ldg((const int4*)src + t);
            int4 d4 = __ldg((const int4*)dst + t);
            int d, k;
            d = clampi(d4.x, N); k = atomicAdd(&g_cursor[d], 1);
            if (k < stride) g_slots[d * stride + k] = clampi(s4.x, N);
            d = clampi(d4.y, N); k = atomicAdd(&g_cursor[d], 1);
            if (k < stride) g_slots[d * stride + k] = clampi(s4.y, N);
            d = clampi(d4.z, N); k = atomicAdd(&g_cursor[d], 1);
            if (k < stride) g_slots[d * stride + k] = clampi(s4.z, N);
            d = clampi(d4.w, N); k = atomicAdd(&g_cursor[d], 1);
            if (k < stride) g_slots[d * stride + k] = clampi(s4.w, N);
        } else {
            #pragma unroll
            for (int j = 0; j < 4; j++)
                if (e0 + j < E) {
                    int s = clampi(__ldg(src + e0 + j), N);
                    int d = clampi(__ldg(dst + e0 + j), N);
                    int k = atomicAdd(&g_cursor[d], 1);
                    if (k < stride) g_slots[d * stride + k] = s;
                }
        }
    } else {
        const long long* src = (const long long*)ei;
        const long long* dst = src + E;
        #pragma unroll
        for (int j = 0; j < 4; j++)
            if (e0 + j < E) {
                int s = clampi((int)__ldg(src + e0 + j), N);
                int d = clampi((int)__ldg(dst + e0 + j), N);
                int k = atomicAdd(&g_cursor[d], 1);
                if (k < stride) g_slots[d * stride + k] = s;
            }
    }
}

// h1 = x @ W1, stored UNSCALED as fp16 — zero dependencies; 2 nodes/thread
__global__ void __launch_bounds__(256) k_gemm1(const float* __restrict__ x,
                                               const float* __restrict__ W1, int N) {
    __shared__ float4 Ws[512];   // W1 as [128 rows][4 float4-cols]
    int t = threadIdx.x;
    Ws[t]       = ((const float4*)W1)[t];
    Ws[t + 256] = ((const float4*)W1)[t + 256];
    __syncthreads();

    int n0 = blockIdx.x * 512 + t;
    int n1 = n0 + 256;
    bool v0 = (n0 < N), v1 = (n1 < N);
    if (!v0) return;

    float4 a0 = make_float4(0.f, 0.f, 0.f, 0.f);
    float4 a1 = a0, a2 = a0, a3 = a0;
    float4 c0 = a0, c1 = a0, c2 = a0, c3 = a0;
    const float4* xr0 = (const float4*)(x + (size_t)n0 * 128);
    const float4* xr1 = (const float4*)(x + (size_t)(v1 ? n1 : n0) * 128);

#pragma unroll 2
    for (int k4 = 0; k4 < 32; k4++) {
        float4 xa = __ldg(&xr0[k4]);
        float4 xb = __ldg(&xr1[k4]);
        const float4* w = &Ws[(k4 * 4) * 4];
#pragma unroll
        for (int j = 0; j < 4; j++) {
            float sa = (j == 0) ? xa.x : (j == 1) ? xa.y : (j == 2) ? xa.z : xa.w;
            float sb = (j == 0) ? xb.x : (j == 1) ? xb.y : (j == 2) ? xb.z : xb.w;
            float4 w0 = w[j * 4 + 0], w1 = w[j * 4 + 1], w2 = w[j * 4 + 2], w3 = w[j * 4 + 3];
            a0 = f4_fma(sa, w0, a0); a1 = f4_fma(sa, w1, a1);
            a2 = f4_fma(sa, w2, a2); a3 = f4_fma(sa, w3, a3);
            c0 = f4_fma(sb, w0, c0); c1 = f4_fma(sb, w1, c1);
            c2 = f4_fma(sb, w2, c2); c3 = f4_fma(sb, w3, c3);
        }
    }

    g_g1h[n0 * 4 + 0] = f4_to_h4(a0); g_g1h[n0 * 4 + 1] = f4_to_h4(a1);
    g_g1h[n0 * 4 + 2] = f4_to_h4(a2); g_g1h[n0 * 4 + 3] = f4_to_h4(a3);
    if (v1) {
        g_g1h[n1 * 4 + 0] = f4_to_h4(c0); g_g1h[n1 * 4 + 1] = f4_to_h4(c1);
        g_g1h[n1 * 4 + 2] = f4_to_h4(c2); g_g1h[n1 * 4 + 3] = f4_to_h4(c3);
    }
}

// after place+gemm1: dinv from cursor; scale g1h rows by dinv in place
__global__ void __launch_bounds__(256) k_dinv_scale(int N, int stride) {
    int gid = blockIdx.x * blockDim.x + threadIdx.x;
    int n = gid >> 2;
    int q = gid & 3;
    if (n >= N) return;
    int deg = min(g_cursor[n], stride);
    float di = rsqrtf((float)(deg + 1));
    if (q == 0) g_dinv[n] = di;
    size_t idx = (size_t)n * 4 + q;
    g_g1h[idx] = f4_to_h4(f4_scale(h4_to_f4(g_g1h[idx]), di));
}

// Pair-layout segmented sum: thread h ∈ {0,1} accumulates features 8h..8h+7
// (one uint4 = 4 half2 per edge). 8-edge chunks: int4 slot loads, fp16
// pairwise-tree reduce per chunk, fp32 chunk flush. Returns lo/hi float4.
struct F8 { float4 lo, hi; };
__device__ __forceinline__ F8 seg_sum_pair(const uint4* __restrict__ gv, int n, int h,
                                           int stride) {
    int deg = min(g_cursor[n], stride);
    const int* srow = &g_slots[n * stride];
    // self loop seed (fp32)
    uint4 sv = __ldg(&gv[(size_t)n * 2 + h]);
    float2 f0 = __half22float2(u2h(sv.x)), f1 = __half22float2(u2h(sv.y));
    float2 f2 = __half22float2(u2h(sv.z)), f3 = __half22float2(u2h(sv.w));
    float4 lo = make_float4(f0.x, f0.y, f1.x, f1.y);
    float4 hi = make_float4(f2.x, f2.y, f3.x, f3.y);

    int e = 0;
    for (; e + 8 <= deg; e += 8) {
        int4 sa = __ldg((const int4*)(srow + e));
        int4 sb = __ldg((const int4*)(srow + e + 4));
        uint4 v0 = __ldg(&gv[(size_t)sa.x * 2 + h]);
        uint4 v1 = __ldg(&gv[(size_t)sa.y * 2 + h]);
        uint4 v2 = __ldg(&gv[(size_t)sa.z * 2 + h]);
        uint4 v3 = __ldg(&gv[(size_t)sa.w * 2 + h]);
        uint4 v4 = __ldg(&gv[(size_t)sb.x * 2 + h]);
        uint4 v5 = __ldg(&gv[(size_t)sb.y * 2 + h]);
        uint4 v6 = __ldg(&gv[(size_t)sb.z * 2 + h]);
        uint4 v7 = __ldg(&gv[(size_t)sb.w * 2 + h]);
        // fp16 pairwise tree per half2 lane (7 HADD2 each)
        __half2 tx = __hadd2(__hadd2(__hadd2(u2h(v0.x), u2h(v1.x)), __hadd2(u2h(v2.x), u2h(v3.x))),
                             __hadd2(__hadd2(u2h(v4.x), u2h(v5.x)), __hadd2(u2h(v6.x), u2h(v7.x))));
        __half2 ty = __hadd2(__hadd2(__hadd2(u2h(v0.y), u2h(v1.y)), __hadd2(u2h(v2.y), u2h(v3.y))),
                             __hadd2(__hadd2(u2h(v4.y), u2h(v5.y)), __hadd2(u2h(v6.y), u2h(v7.y))));
        __half2 tz = __hadd2(__hadd2(__hadd2(u2h(v0.z), u2h(v1.z)), __hadd2(u2h(v2.z), u2h(v3.z))),
                             __hadd2(__hadd2(u2h(v4.z), u2h(v5.z)), __hadd2(u2h(v6.z), u2h(v7.z))));
        __half2 tw = __hadd2(__hadd2(__hadd2(u2h(v0.w), u2h(v1.w)), __hadd2(u2h(v2.w), u2h(v3.w))),
                             __hadd2(__hadd2(u2h(v4.w), u2h(v5.w)), __hadd2(u2h(v6.w), u2h(v7.w))));
        float2 gx = __half22float2(tx), gy = __half22float2(ty);
        float2 gz = __half22float2(tz), gw = __half22float2(tw);
        lo.x += gx.x; lo.y += gx.y; lo.z += gy.x; lo.w += gy.y;
        hi.x += gz.x; hi.y += gz.y; hi.z += gw.x; hi.w += gw.y;
    }
    for (; e < deg; e++) {
        int s = __ldg(&srow[e]);
        uint4 v = __ldg(&gv[(size_t)s * 2 + h]);
        float2 a0 = __half22float2(u2h(v.x)), a1 = __half22float2(u2h(v.y));
        float2 a2 = __half22float2(u2h(v.z)), a3 = __half22float2(u2h(v.w));
        lo.x += a0.x; lo.y += a0.y; lo.z += a1.x; lo.w += a1.y;
        hi.x += a2.x; hi.y += a2.y; hi.z += a3.x; hi.w += a3.y;
    }
    F8 r; r.lo = lo; r.hi = hi;
    return r;
}

// reduce layer1 (pair layout) + fused: t = relu(dinv*acc + b1); h2 = t @ W2; g2 = h2*dinv
// No early returns (pair shuffles); stores predicated.
__global__ void __launch_bounds__(256) k_reduce1(const float* __restrict__ b1,
                                                 const float* __restrict__ W2, int N,
                                                 int stride) {
    __shared__ float4 W2s[64];
    __shared__ float4 b1s[4];
    int t = threadIdx.x;
    if (t < 64) W2s[t] = ((const float4*)W2)[t];
    if (t < 4)  b1s[t] = ((const float4*)b1)[t];
    __syncthreads();

    int gid = blockIdx.x * 256 + t;
    int n = gid >> 1;
    int h = gid & 1;
    bool valid = (n < N);
    int nc = valid ? n : (N - 1);

    F8 acc = seg_sum_pair((const uint4*)g_g1h, nc, h, stride);
    float di = g_dinv[nc];
    float4 olo = f4_fma(di, acc.lo, b1s[2 * h]);
    float4 ohi = f4_fma(di, acc.hi, b1s[2 * h + 1]);
    float tv[8];
    tv[0] = fmaxf(olo.x, 0.f); tv[1] = fmaxf(olo.y, 0.f);
    tv[2] = fmaxf(olo.z, 0.f); tv[3] = fmaxf(olo.w, 0.f);
    tv[4] = fmaxf(ohi.x, 0.f); tv[5] = fmaxf(ohi.y, 0.f);
    tv[6] = fmaxf(ohi.z, 0.f); tv[7] = fmaxf(ohi.w, 0.f);

    // 16x16 GEMM across the lane pair: j's owner lane = (lane & ~1) | (j>>3)
    float4 alo = make_float4(0.f, 0.f, 0.f, 0.f);
    float4 ahi = alo;
    int lane = t & 31;
    int pbase = lane & ~1;
#pragma unroll
    for (int j = 0; j < 16; j++) {
        float tj = __shfl_sync(0xFFFFFFFFu, tv[j & 7], pbase + (j >> 3));
        alo = f4_fma(tj, W2s[j * 4 + 2 * h], alo);
        ahi = f4_fma(tj, W2s[j * 4 + 2 * h + 1], ahi);
    }
    if (valid) {
        uint2 plo = f4_to_h4(f4_scale(alo, di));
        uint2 phi = f4_to_h4(f4_scale(ahi, di));
        uint4 pk; pk.x = plo.x; pk.y = plo.y; pk.z = phi.x; pk.w = phi.y;
        ((uint4*)g_g2h)[(size_t)n * 2 + h] = pk;
    }
}

// reduce layer2 (pair layout) + fused mean-pool accumulate (fp32 pool)
__global__ void __launch_bounds__(256) k_reduce2(const void* __restrict__ batch,
                                                 const float* __restrict__ b2, int N,
                                                 int stride) {
    int gid = blockIdx.x * blockDim.x + threadIdx.x;
    int n = gid >> 1;
    int h = gid & 1;
    if (n >= N) return;

    F8 acc = seg_sum_pair((const uint4*)g_g2h, n, h, stride);
    float di = g_dinv[n];
    float4 ylo = f4_fma(di, acc.lo, __ldg(&((const float4*)b2)[2 * h]));
    float4 yhi = f4_fma(di, acc.hi, __ldg(&((const float4*)b2)[2 * h + 1]));

    int b = load_idx(batch, n, g_is32_b, NG);
    red_add_v4(&g_pool[b * 4 + 2 * h], ylo);
    red_add_v4(&g_pool[b * 4 + 2 * h + 1], yhi);
    if (h == 0) atomicAdd(&g_cnt[b], 1);
}

__global__ void __launch_bounds__(256) k_final(float* __restrict__ out) {
    int i = blockIdx.x * blockDim.x + threadIdx.x;
    if (i >= NG * 16) return;
    int g = i >> 4;
    float c = fmaxf((float)g_cnt[g], 1.0f);
    float s = ((const float*)g_pool)[i] / c;
    out[i] = 1.0f / (1.0f + expf(-s));
}

// ---------------- launch ----------------
extern "C" void kernel_launch(void* const* d_in, const int* in_sizes, int n_in,
                              void* d_out, int out_size) {
    static cudaStream_t s_aux = nullptr;
    static cudaEvent_t  s_fork = nullptr, s_join = nullptr;
    static bool s_tried = false;
    if (!s_tried) {
        s_tried = true;
        if (cudaStreamCreateWithFlags(&s_aux, cudaStreamNonBlocking) != cudaSuccess)
            s_aux = nullptr;
        if (s_aux) {
            if (cudaEventCreateWithFlags(&s_fork, cudaEventDisableTiming) != cudaSuccess ||
                cudaEventCreateWithFlags(&s_join, cudaEventDisableTiming) != cudaSuccess)
                s_aux = nullptr;
        }
    }

    const float* x     = (const float*)d_in[0];
    const void*  ei    = d_in[1];               // [2, E] int32 OR int64 (probed)
    const void*  batch = d_in[2];               // [N]    int32 OR int64 (probed)
    const float* W1    = (const float*)d_in[3];
    const float* b1    = (const float*)d_in[4];
    const float* W2    = (const float*)d_in[5];
    const float* b2    = (const float*)d_in[6];
    float* out = (float*)d_out;

    int N = in_sizes[0] / 128;
    int E = in_sizes[1] / 2;

    int stride = 128;
    while ((long long)stride * N > MAXSLOTS && stride > 8) stride >>= 1;

    int nb_nodes = (N + 255) / 256;
    int nb_edge4 = (E / 4 + 256) / 256;
    int nb_node4 = (4 * N + 255) / 256;
    int nb_node2 = (2 * N + 255) / 256;
    int nb_g     = (N + 511) / 512;

    if (s_aux) {
        cudaEventRecord(s_fork, 0);
        cudaStreamWaitEvent(s_aux, s_fork, 0);
        k_gemm1<<<nb_g, 256, 0, s_aux>>>(x, W1, N);   // independent: overlaps below
    }

    k_init<<<nb_nodes, 256>>>(N);
    {
        int nsampE = min(2048, E);
        long long strideE = (E > nsampE) ? (E / nsampE) : 1;
        long long offB = (N > 512) ? (long long)((N - 512) & ~1) : 0;
        int nsampB = (int)((N - offB) / 2);
        k_detect_all<<<9, 256>>>((const unsigned*)ei, strideE, nsampE,
                                 (const unsigned*)batch, offB, nsampB);
    }
    k_place<<<nb_edge4, 256>>>(ei, E, N, stride);

    if (s_aux) {
        cudaEventRecord(s_join, s_aux);
        cudaStreamWaitEvent(0, s_join, 0);
    } else {
        k_gemm1<<<nb_g, 256>>>(x, W1, N);
    }

    k_dinv_scale<<<nb_node4, 256>>>(N, stride);
    k_reduce1<<<nb_node2, 256>>>(b1, W2, N, stride);
    k_reduce2<<<nb_node2, 256>>>(batch, b2, N, stride);
    k_final<<<(NG * 16 + 255) / 256, 256>>>(out);
}